// round 5
// baseline (speedup 1.0000x reference)
#include <cuda_runtime.h>
#include <cstdint>

// Problem constants (fixed by setup_inputs: N=4, M=8192, D=64, k=16)
#define M_PTS   8192
#define D_DIM   64
#define K_NN    16
#define TILE_C  128        // candidates per shared-memory tile
#define BLOCK_T 256        // threads per block = queries per block
#define N_BATCH 4
#define TOTAL_PTS (N_BATCH * M_PTS)
#define NMK      (TOTAL_PTS * K_NN)   // 524288 edges per output array

// ---------------------------------------------------------------------------
// Kernel 0: diagnostic pre-fill (FLOAT output). dst region fully correct;
// src region self-ids (correct at j=0 only). Overwritten by main kernel.
// ---------------------------------------------------------------------------
__global__ void prefill_kernel(float* __restrict__ out) {
    int i = blockIdx.x * blockDim.x + threadIdx.x;
    if (i < NMK) {
        float node = (float)(i >> 4);   // / K_NN
        out[i]       = node;            // src region: self id (correct at j=0)
        out[NMK + i] = node;            // dst region: fully correct
    }
}

// ---------------------------------------------------------------------------
// Kernel 1: brute-force KNN. 1 thread = 1 query; candidate tile in shared
// (float4-typed => 16B alignment guaranteed); top-16 sorted in registers.
// Output written as FLOAT (checker dtype is float32).
// ---------------------------------------------------------------------------
__global__ __launch_bounds__(BLOCK_T, 1)
void knn_kernel(const float* __restrict__ x,
                float* __restrict__ out_src,
                float* __restrict__ out_dst) {
    __shared__ float4 s_c4[TILE_C * D_DIM / 4];  // candidate tile, 16B-aligned
    __shared__ float  s_cx2[TILE_C];             // candidate squared norms

    float* s_c = reinterpret_cast<float*>(s_c4); // scalar alias for fills

    const int tid  = threadIdx.x;
    const int lane = tid & 31;
    const int warp = tid >> 5;                    // 0..7
    const int q    = blockIdx.x * BLOCK_T + tid;  // global query id
    const int n    = q >> 13;                     // / M_PTS  (M=8192)
    const int qm   = q & (M_PTS - 1);             // query index within batch
    const float* xb = x + (size_t)n * M_PTS * D_DIM;

    // query vector in registers — scalar global loads (no alignment assumption)
    float qv[D_DIM];
    {
        const float* qp = xb + (size_t)qm * D_DIM;
#pragma unroll
        for (int j = 0; j < D_DIM; ++j) qv[j] = qp[j];
    }
    float qx2 = 0.f;
#pragma unroll
    for (int j = 0; j < D_DIM; ++j) qx2 += qv[j] * qv[j];

    // sorted top-k (ascending distance; strict < keeps earlier/lower index on ties)
    float bd[K_NN];
    int   bi[K_NN];
#pragma unroll
    for (int j = 0; j < K_NN; ++j) { bd[j] = __int_as_float(0x7f800000); bi[j] = 0; }

    for (int t0 = 0; t0 < M_PTS; t0 += TILE_C) {
        __syncthreads();
        // cooperative tile load: 8192 floats, scalar coalesced copies
        {
            const float* g = xb + (size_t)t0 * D_DIM;
#pragma unroll
            for (int j = 0; j < (TILE_C * D_DIM) / BLOCK_T; ++j)
                s_c[tid + j * BLOCK_T] = g[tid + j * BLOCK_T];
        }
        __syncthreads();
        // candidate norms: warp w handles candidates [w*16, w*16+16)
        // lane l reads s_c[c*64 + l] and s_c[c*64 + 32 + l] -> conflict-free
#pragma unroll
        for (int cc = 0; cc < TILE_C / 8; ++cc) {
            int c = warp * (TILE_C / 8) + cc;
            float v0 = s_c[c * D_DIM + lane];
            float v1 = s_c[c * D_DIM + 32 + lane];
            float p = v0 * v0 + v1 * v1;
#pragma unroll
            for (int s = 16; s > 0; s >>= 1)
                p += __shfl_xor_sync(0xffffffffu, p, s);
            if (lane == 0) s_cx2[c] = p;
        }
        __syncthreads();

#pragma unroll 1
        for (int c = 0; c < TILE_C; ++c) {
            const float4* cv = s_c4 + c * (D_DIM / 4);  // aligned by type
            // 4 lane-split accumulators: same-accum FMAs are 4 instrs apart
            float a0 = 0.f, a1 = 0.f, a2 = 0.f, a3 = 0.f;
#pragma unroll
            for (int j = 0; j < D_DIM / 4; ++j) {
                float4 v = cv[j];
                a0 = fmaf(qv[4 * j + 0], v.x, a0);
                a1 = fmaf(qv[4 * j + 1], v.y, a1);
                a2 = fmaf(qv[4 * j + 2], v.z, a2);
                a3 = fmaf(qv[4 * j + 3], v.w, a3);
            }
            float dot = (a0 + a1) + (a2 + a3);
            float d = (qx2 + s_cx2[c]) - 2.0f * dot;

            if (d < bd[K_NN - 1]) {
                bd[K_NN - 1] = d;
                bi[K_NN - 1] = t0 + c;
#pragma unroll
                for (int j = K_NN - 1; j > 0; --j) {
                    if (bd[j] < bd[j - 1]) {
                        float td = bd[j]; bd[j] = bd[j - 1]; bd[j - 1] = td;
                        int   ti = bi[j]; bi[j] = bi[j - 1]; bi[j - 1] = ti;
                    }
                }
            }
        }
    }

    // emit edges as FLOAT: src = neighbor global id, dst = this node's id
    const int base = q * K_NN;
    const int off  = n * M_PTS;
#pragma unroll
    for (int j = 0; j < K_NN; ++j) {
        out_src[base + j] = (float)(bi[j] + off);
        out_dst[base + j] = (float)q;
    }
}

// ---------------------------------------------------------------------------
// Launch
// ---------------------------------------------------------------------------
extern "C" void kernel_launch(void* const* d_in, const int* in_sizes, int n_in,
                              void* d_out, int out_size) {
    // x is the largest input (N*M*D floats); scalar k may precede or follow.
    int xi = 0;
    for (int i = 1; i < n_in; ++i)
        if (in_sizes[i] > in_sizes[xi]) xi = i;
    const float* x = (const float*)d_in[xi];

    float* out = (float*)d_out;

    prefill_kernel<<<(NMK + 255) / 256, 256>>>(out);
    knn_kernel<<<TOTAL_PTS / BLOCK_T, BLOCK_T>>>(x, out, out + NMK);
}

// round 6
// speedup vs baseline: 1.1815x; 1.1815x over previous
#include <cuda_runtime.h>
#include <cstdint>

// Problem constants (fixed by setup_inputs: N=4, M=8192, D=64, k=16)
#define M_PTS   8192
#define D_DIM   64
#define K_NN    16
#define TILE_C  64         // candidates per shared-memory tile (16 KB)
#define BLOCK_T 32         // 1 warp per block = 32 queries
#define N_BATCH 4
#define TOTAL_PTS (N_BATCH * M_PTS)
#define NMK      (TOTAL_PTS * K_NN)   // 524288 edges per output array

// Squared norms, computed once (allocation-free rule: __device__ global)
__device__ float g_sqnorm[TOTAL_PTS];

// ---------------------------------------------------------------------------
// Kernel 1: squared norms per point (sequential sum, float4 loads)
// ---------------------------------------------------------------------------
__global__ void sqnorm_kernel(const float* __restrict__ x) {
    int i = blockIdx.x * blockDim.x + threadIdx.x;
    if (i >= TOTAL_PTS) return;
    const float4* xv = reinterpret_cast<const float4*>(x + (size_t)i * D_DIM);
    float s = 0.f;
#pragma unroll
    for (int j = 0; j < D_DIM / 4; ++j) {
        float4 v = xv[j];
        s += v.x * v.x + v.y * v.y + v.z * v.z + v.w * v.w;
    }
    g_sqnorm[i] = s;
}

// ---------------------------------------------------------------------------
// Kernel 2: brute-force KNN. 1-warp blocks (32 queries), 12 blocks/SM.
// Candidate tile in float4 shared; 2 candidates per iter (8 accumulators).
// Top-16 kept sorted in registers; output written as float32.
// ---------------------------------------------------------------------------
__global__ __launch_bounds__(BLOCK_T, 12)
void knn_kernel(const float* __restrict__ x,
                float* __restrict__ out_src,
                float* __restrict__ out_dst) {
    __shared__ float4 s_c4[TILE_C * D_DIM / 4];  // 16 KB candidate tile
    __shared__ float  s_cx2[TILE_C];             // candidate squared norms

    const int tid = threadIdx.x;                 // 0..31
    const int q   = blockIdx.x * BLOCK_T + tid;  // global query id
    const int n   = q >> 13;                     // / M_PTS
    const int qm  = q & (M_PTS - 1);
    const float* xb = x + (size_t)n * M_PTS * D_DIM;

    // query vector in registers (rows are 256B-aligned -> float4 is safe)
    float4 qv[D_DIM / 4];
    {
        const float4* qp = reinterpret_cast<const float4*>(xb + (size_t)qm * D_DIM);
#pragma unroll
        for (int j = 0; j < D_DIM / 4; ++j) qv[j] = qp[j];
    }
    const float qx2 = g_sqnorm[q];

    // sorted top-k (ascending; strict < keeps earlier/lower index on ties)
    float bd[K_NN];
    int   bi[K_NN];
#pragma unroll
    for (int j = 0; j < K_NN; ++j) { bd[j] = __int_as_float(0x7f800000); bi[j] = 0; }

    for (int t0 = 0; t0 < M_PTS; t0 += TILE_C) {
        __syncthreads();
        // tile load: TILE_C*D_DIM/4 = 1024 float4 / 32 threads = 32 each
        {
            const float4* g4 = reinterpret_cast<const float4*>(xb + (size_t)t0 * D_DIM);
#pragma unroll
            for (int j = 0; j < (TILE_C * D_DIM / 4) / BLOCK_T; ++j)
                s_c4[tid + j * BLOCK_T] = g4[tid + j * BLOCK_T];
            s_cx2[tid]          = g_sqnorm[n * M_PTS + t0 + tid];
            s_cx2[tid + 32]     = g_sqnorm[n * M_PTS + t0 + tid + 32];
        }
        __syncthreads();

#pragma unroll 1
        for (int c = 0; c < TILE_C; c += 2) {
            const float4* cv0 = s_c4 + c * (D_DIM / 4);
            const float4* cv1 = cv0 + (D_DIM / 4);
            // two independent accumulator quads -> 2 parallel FFMA chains
            float a0 = 0.f, a1 = 0.f, a2 = 0.f, a3 = 0.f;
            float b0 = 0.f, b1 = 0.f, b2 = 0.f, b3 = 0.f;
#pragma unroll
            for (int j = 0; j < D_DIM / 4; ++j) {
                float4 u = cv0[j];
                float4 v = cv1[j];
                a0 = fmaf(qv[j].x, u.x, a0);
                b0 = fmaf(qv[j].x, v.x, b0);
                a1 = fmaf(qv[j].y, u.y, a1);
                b1 = fmaf(qv[j].y, v.y, b1);
                a2 = fmaf(qv[j].z, u.z, a2);
                b2 = fmaf(qv[j].z, v.z, b2);
                a3 = fmaf(qv[j].w, u.w, a3);
                b3 = fmaf(qv[j].w, v.w, b3);
            }
            float d0 = (qx2 + s_cx2[c])     - 2.0f * ((a0 + a1) + (a2 + a3));
            float d1 = (qx2 + s_cx2[c + 1]) - 2.0f * ((b0 + b1) + (b2 + b3));

            if (d0 < bd[K_NN - 1]) {
                bd[K_NN - 1] = d0; bi[K_NN - 1] = t0 + c;
#pragma unroll
                for (int j = K_NN - 1; j > 0; --j) {
                    if (bd[j] < bd[j - 1]) {
                        float td = bd[j]; bd[j] = bd[j - 1]; bd[j - 1] = td;
                        int   ti = bi[j]; bi[j] = bi[j - 1]; bi[j - 1] = ti;
                    }
                }
            }
            if (d1 < bd[K_NN - 1]) {
                bd[K_NN - 1] = d1; bi[K_NN - 1] = t0 + c + 1;
#pragma unroll
                for (int j = K_NN - 1; j > 0; --j) {
                    if (bd[j] < bd[j - 1]) {
                        float td = bd[j]; bd[j] = bd[j - 1]; bd[j - 1] = td;
                        int   ti = bi[j]; bi[j] = bi[j - 1]; bi[j - 1] = ti;
                    }
                }
            }
        }
    }

    // emit edges as float: src = neighbor global id, dst = this node's id
    const int base = q * K_NN;
    const int off  = n * M_PTS;
#pragma unroll
    for (int j = 0; j < K_NN; ++j) {
        out_src[base + j] = (float)(bi[j] + off);
        out_dst[base + j] = (float)q;
    }
}

// ---------------------------------------------------------------------------
// Launch
// ---------------------------------------------------------------------------
extern "C" void kernel_launch(void* const* d_in, const int* in_sizes, int n_in,
                              void* d_out, int out_size) {
    // x is the largest input (N*M*D floats); scalar k may precede or follow.
    int xi = 0;
    for (int i = 1; i < n_in; ++i)
        if (in_sizes[i] > in_sizes[xi]) xi = i;
    const float* x = (const float*)d_in[xi];

    float* out = (float*)d_out;

    sqnorm_kernel<<<(TOTAL_PTS + 255) / 256, 256>>>(x);
    knn_kernel<<<TOTAL_PTS / BLOCK_T, BLOCK_T>>>(x, out, out + NMK);
}

// round 7
// speedup vs baseline: 1.2770x; 1.0808x over previous
#include <cuda_runtime.h>
#include <cstdint>

// Problem constants (fixed by setup_inputs: N=4, M=8192, D=64, k=16)
#define M_PTS   8192
#define D_DIM   64
#define K_NN    16
#define TILE_C  64         // candidates per shared tile (16 KB)
#define BLOCK_T 32         // 1 warp per block
#define N_BATCH 4
#define SPLIT   4          // candidate-dimension split for occupancy
#define RANGE   (M_PTS / SPLIT)       // 2048 candidates per block
#define TOTAL_PTS (N_BATCH * M_PTS)   // 32768
#define NMK     (TOTAL_PTS * K_NN)    // 524288 edges per output array

typedef unsigned long long u64;

// Scratch (allocation-free rule: __device__ globals)
__device__ float g_sqnorm[TOTAL_PTS];
__device__ float g_pd[SPLIT * NMK];   // partial top-k distances
__device__ int   g_pi[SPLIT * NMK];   // partial top-k global ids

// ---------------------------------------------------------------------------
// Packed fp32x2 helpers (sm_103a FFMA2 — only reachable via PTX)
// ---------------------------------------------------------------------------
__device__ __forceinline__ u64 fma2(u64 a, u64 b, u64 c) {
    u64 d;
    asm("fma.rn.f32x2 %0, %1, %2, %3;" : "=l"(d) : "l"(a), "l"(b), "l"(c));
    return d;
}
// ((a.lo+a.hi) + (b.lo+b.hi)) — same association as the scalar baseline
__device__ __forceinline__ float hsum2x2(u64 a, u64 b) {
    float a0, a1, b0, b1;
    asm("mov.b64 {%0,%1}, %2;" : "=f"(a0), "=f"(a1) : "l"(a));
    asm("mov.b64 {%0,%1}, %2;" : "=f"(b0), "=f"(b1) : "l"(b));
    return (a0 + a1) + (b0 + b1);
}

// ---------------------------------------------------------------------------
// Kernel 1: squared norms per point
// ---------------------------------------------------------------------------
__global__ void sqnorm_kernel(const float* __restrict__ x) {
    int i = blockIdx.x * blockDim.x + threadIdx.x;
    if (i >= TOTAL_PTS) return;
    const float4* xv = reinterpret_cast<const float4*>(x + (size_t)i * D_DIM);
    float s = 0.f;
#pragma unroll
    for (int j = 0; j < D_DIM / 4; ++j) {
        float4 v = xv[j];
        s += v.x * v.x + v.y * v.y + v.z * v.z + v.w * v.w;
    }
    g_sqnorm[i] = s;
}

// ---------------------------------------------------------------------------
// Kernel 2: split-K brute-force KNN. blockIdx.x = query warp, blockIdx.y =
// candidate split. f32x2 packed dot products; sorted top-16 in registers;
// partial results to scratch.
// ---------------------------------------------------------------------------
__global__ __launch_bounds__(BLOCK_T, 12)
void knn_kernel(const float* __restrict__ x) {
    __shared__ float4 s_c4[TILE_C * D_DIM / 4];  // 16 KB candidate tile
    __shared__ float  s_cx2[TILE_C];

    const int tid    = threadIdx.x;                 // 0..31
    const int q      = blockIdx.x * BLOCK_T + tid;  // global query id
    const int sp     = blockIdx.y;                  // split id
    const int n      = q >> 13;                     // / M_PTS
    const int qm     = q & (M_PTS - 1);
    const int c_base = sp * RANGE;
    const float* xb  = x + (size_t)n * M_PTS * D_DIM;

    // query vector as 32 packed f32x2 registers (rows are 256B aligned)
    u64 qv[D_DIM / 2];
    {
        const ulonglong2* qp =
            reinterpret_cast<const ulonglong2*>(xb + (size_t)qm * D_DIM);
#pragma unroll
        for (int j = 0; j < D_DIM / 4; ++j) {
            ulonglong2 t = qp[j];
            qv[2 * j]     = t.x;   // dims 4j, 4j+1
            qv[2 * j + 1] = t.y;   // dims 4j+2, 4j+3
        }
    }
    const float qx2 = g_sqnorm[q];

    // sorted top-k (ascending; strict < keeps earlier/lower index on ties)
    float bd[K_NN];
    int   bi[K_NN];
#pragma unroll
    for (int j = 0; j < K_NN; ++j) { bd[j] = __int_as_float(0x7f800000); bi[j] = 0; }

    for (int t0 = 0; t0 < RANGE; t0 += TILE_C) {
        __syncthreads();
        {
            const float4* g4 = reinterpret_cast<const float4*>(
                xb + (size_t)(c_base + t0) * D_DIM);
#pragma unroll
            for (int j = 0; j < (TILE_C * D_DIM / 4) / BLOCK_T; ++j)
                s_c4[tid + j * BLOCK_T] = g4[tid + j * BLOCK_T];
            s_cx2[tid]      = g_sqnorm[n * M_PTS + c_base + t0 + tid];
            s_cx2[tid + 32] = g_sqnorm[n * M_PTS + c_base + t0 + tid + 32];
        }
        __syncthreads();
        const ulonglong2* sc = reinterpret_cast<const ulonglong2*>(s_c4);

#pragma unroll 1
        for (int c = 0; c < TILE_C; c += 2) {
            const ulonglong2* cv0 = sc + c * (D_DIM / 4);
            const ulonglong2* cv1 = cv0 + (D_DIM / 4);
            // packed accumulator chains: a01=(x,y) lanes, a23=(z,w) lanes
            u64 a01 = 0, a23 = 0, b01 = 0, b23 = 0;  // 0ull == packed (0.f,0.f)
#pragma unroll
            for (int j = 0; j < D_DIM / 4; ++j) {
                ulonglong2 u = cv0[j];
                ulonglong2 v = cv1[j];
                a01 = fma2(qv[2 * j],     u.x, a01);
                b01 = fma2(qv[2 * j],     v.x, b01);
                a23 = fma2(qv[2 * j + 1], u.y, a23);
                b23 = fma2(qv[2 * j + 1], v.y, b23);
            }
            float d0 = fmaf(-2.f, hsum2x2(a01, a23), qx2 + s_cx2[c]);
            float d1 = fmaf(-2.f, hsum2x2(b01, b23), qx2 + s_cx2[c + 1]);

            if (d0 < bd[K_NN - 1]) {
                bd[K_NN - 1] = d0; bi[K_NN - 1] = c_base + t0 + c;
#pragma unroll
                for (int j = K_NN - 1; j > 0; --j) {
                    if (bd[j] < bd[j - 1]) {
                        float td = bd[j]; bd[j] = bd[j - 1]; bd[j - 1] = td;
                        int   ti = bi[j]; bi[j] = bi[j - 1]; bi[j - 1] = ti;
                    }
                }
            }
            if (d1 < bd[K_NN - 1]) {
                bd[K_NN - 1] = d1; bi[K_NN - 1] = c_base + t0 + c + 1;
#pragma unroll
                for (int j = K_NN - 1; j > 0; --j) {
                    if (bd[j] < bd[j - 1]) {
                        float td = bd[j]; bd[j] = bd[j - 1]; bd[j - 1] = td;
                        int   ti = bi[j]; bi[j] = bi[j - 1]; bi[j - 1] = ti;
                    }
                }
            }
        }
    }

    // write partial top-k (ids made global across batches here)
    const int pb  = (sp * TOTAL_PTS + q) * K_NN;
    const int off = n * M_PTS;
#pragma unroll
    for (int j = 0; j < K_NN; ++j) {
        g_pd[pb + j] = bd[j];
        g_pi[pb + j] = bi[j] + off;
    }
}

// ---------------------------------------------------------------------------
// Kernel 3: 4-way sorted merge of partial top-16 lists -> final edges (float)
// Tie-break: equal distance -> lower global index (matches jax top_k).
// ---------------------------------------------------------------------------
__global__ void merge_kernel(float* __restrict__ out_src,
                             float* __restrict__ out_dst) {
    int q = blockIdx.x * blockDim.x + threadIdx.x;
    if (q >= TOTAL_PTS) return;
    int p[SPLIT];
#pragma unroll
    for (int s = 0; s < SPLIT; ++s) p[s] = 0;

    const float fq = (float)q;
#pragma unroll 1
    for (int j = 0; j < K_NN; ++j) {
        float best  = __int_as_float(0x7f800000);
        int   besti = 0x7fffffff;
        int   bs    = 0;
#pragma unroll
        for (int s = 0; s < SPLIT; ++s) {
            if (p[s] < K_NN) {
                int o = (s * TOTAL_PTS + q) * K_NN + p[s];
                float dd = g_pd[o];
                int   ii = g_pi[o];
                if (dd < best || (dd == best && ii < besti)) {
                    best = dd; besti = ii; bs = s;
                }
            }
        }
        p[bs]++;
        out_src[q * K_NN + j] = (float)besti;
        out_dst[q * K_NN + j] = fq;
    }
}

// ---------------------------------------------------------------------------
// Launch
// ---------------------------------------------------------------------------
extern "C" void kernel_launch(void* const* d_in, const int* in_sizes, int n_in,
                              void* d_out, int out_size) {
    // x is the largest input (N*M*D floats); scalar k may precede or follow.
    int xi = 0;
    for (int i = 1; i < n_in; ++i)
        if (in_sizes[i] > in_sizes[xi]) xi = i;
    const float* x = (const float*)d_in[xi];

    float* out = (float*)d_out;

    sqnorm_kernel<<<(TOTAL_PTS + 255) / 256, 256>>>(x);
    dim3 grid(TOTAL_PTS / BLOCK_T, SPLIT);
    knn_kernel<<<grid, BLOCK_T>>>(x);
    merge_kernel<<<(TOTAL_PTS + 255) / 256, 256>>>(out, out + NMK);
}